// round 4
// baseline (speedup 1.0000x reference)
#include <cuda_runtime.h>
#include <cuda_bf16.h>
#include <math.h>

// Global accumulators (zero at module load; last block resets them each run,
// so every graph replay starts from zeros).
__device__ float        g_bins[128];
__device__ int          g_cnt[128];
__device__ float        g_cls_sum;
__device__ float        g_box_sum;
__device__ unsigned int g_arrive;

// ---------------------------------------------------------------------------
// Single fused kernel: one block (256 thr) per RoI r.
//   warps 0-6 (tid 0..195 active): RoI-align bilinear target + BCE (float4)
//   warp 7: cls CE for row r  (+ box smooth-L1 if r < num_pos)
//   block reduce -> atomicAdd into global accumulators
//   LAST block: writes all outputs and resets accumulators (no writer launch).
// ---------------------------------------------------------------------------
template<int MO>
__global__ void __launch_bounds__(256) fused_kernel(
        const float* __restrict__ class_logit,
        const float* __restrict__ box_regression,
        const float* __restrict__ regression_target,
        const float* __restrict__ mask_logit,
        const float* __restrict__ proposal,
        const float* __restrict__ gt_mask,
        const int* __restrict__ matched_idx,
        const int* __restrict__ label,
        float* __restrict__ out,
        int C, int Hh, int Ww, int Mo_rt, int num_pos, int R, int G) {
    const int Mo = (MO > 0) ? MO : Mo_rt;
    const int P  = Mo * Mo;
    int r    = blockIdx.x;
    int tid  = threadIdx.x;
    int lane = tid & 31;
    int w    = tid >> 5;
    __shared__ float sh[8];
    __shared__ bool  s_last;

    int lab = __ldg(&label[r]);
    int b   = __ldg(&matched_idx[r]);

    float acc = 0.0f;

    if (w == 7) {
        // ---- classification CE for this row ----
        const float* row = class_logit + (size_t)r * C;
        float mx = -INFINITY;
        for (int c = lane; c < C; c += 32) mx = fmaxf(mx, __ldg(row + c));
        #pragma unroll
        for (int o = 16; o; o >>= 1) mx = fmaxf(mx, __shfl_xor_sync(0xFFFFFFFFu, mx, o));
        float s2 = 0.0f;
        for (int c = lane; c < C; c += 32) s2 += __expf(__ldg(row + c) - mx);
        #pragma unroll
        for (int o = 16; o; o >>= 1) s2 += __shfl_xor_sync(0xFFFFFFFFu, s2, o);
        if (lane == 0) atomicAdd(&g_cls_sum, mx + __logf(s2) - __ldg(row + lab));

        // ---- box smooth-L1 for this row (if positive) ----
        if (r < num_pos) {
            float term = 0.0f;
            if (lane < 4) {
                float pred = __ldg(&box_regression[(size_t)r * (C * 4) + lab * 4 + lane]);
                float tgt  = __ldg(&regression_target[r * 4 + lane]);
                float d = fabsf(pred - tgt);
                term = (d < 1.0f) ? 0.5f * d * d : d - 0.5f;
            }
            #pragma unroll
            for (int o = 2; o; o >>= 1) term += __shfl_xor_sync(0xFFFFFFFFu, term, o);
            if (lane == 0) atomicAdd(&g_box_sum, term);
        }
        if (lane == 0) sh[7] = 0.0f;
    } else {
        // ---- mask BCE ----
        float4 box = *(const float4*)(proposal + (size_t)r * 4);
        float x1 = box.x, y1 = box.y, x2 = box.z, y2 = box.w;
        float invMo = 1.0f / (float)Mo;
        float sx = (x2 - x1) * invMo;
        float sy = (y2 - y1) * invMo;
        const float* sel = mask_logit + ((size_t)r * C + lab) * P;
        const float* fm  = gt_mask + (size_t)b * Hh * Ww;

        float prod = 1.0f;

        if (MO == 28) {
            const int q = tid;                 // tid 0..195 active (196 float4 chunks)
            if (q < 196) {
                int iy  = q / 7;
                int ix0 = (q - iy * 7) << 2;
                float y = fmaf((float)iy + 0.5f, sy, y1);
                float4 s4 = __ldg((const float4*)sel + q);

                bool vy = (y > -1.0f) & (y < (float)Hh);
                float yc = fminf(fmaxf(y, 0.0f), (float)(Hh - 1));
                int y0 = (int)yc;
                int yi = min(y0 + 1, Hh - 1);
                float ly = yc - (float)y0;
                const float* r0 = fm + (size_t)y0 * Ww;
                const float* r1 = fm + (size_t)yi * Ww;

                // branch-free: all gathers issue unconditionally (coords clamped)
                #pragma unroll
                for (int j = 0; j < 4; j++) {
                    float s = (j == 0) ? s4.x : (j == 1) ? s4.y : (j == 2) ? s4.z : s4.w;
                    float x = fmaf((float)(ix0 + j) + 0.5f, sx, x1);
                    bool valid = vy & (x > -1.0f) & (x < (float)Ww);
                    float xc = fminf(fmaxf(x, 0.0f), (float)(Ww - 1));
                    int x0 = (int)xc;
                    int xi = min(x0 + 1, Ww - 1);
                    float lx = xc - (float)x0;
                    float v00 = __ldg(r0 + x0);
                    float v01 = __ldg(r0 + xi);
                    float v10 = __ldg(r1 + x0);
                    float v11 = __ldg(r1 + xi);
                    float top = fmaf(lx, v01 - v00, v00);
                    float bot = fmaf(lx, v11 - v10, v10);
                    float t = fmaf(ly, bot - top, top);
                    t = valid ? t : 0.0f;
                    acc  += fmaxf(s, 0.0f) - s * t;
                    prod *= 1.0f + __expf(-fabsf(s));
                }
            }
        } else {
            for (int p = tid; p < P; p += 224) {
                int iy = p / Mo;
                int ix = p - iy * Mo;
                float x = fmaf((float)ix + 0.5f, sx, x1);
                float y = fmaf((float)iy + 0.5f, sy, y1);
                bool valid = (x > -1.0f) & (x < (float)Ww) & (y > -1.0f) & (y < (float)Hh);
                float xc = fminf(fmaxf(x, 0.0f), (float)(Ww - 1));
                float yc = fminf(fmaxf(y, 0.0f), (float)(Hh - 1));
                int x0 = (int)xc, y0 = (int)yc;
                int xi = min(x0 + 1, Ww - 1);
                int yi = min(y0 + 1, Hh - 1);
                float lx = xc - (float)x0, ly = yc - (float)y0;
                const float* r0 = fm + (size_t)y0 * Ww;
                const float* r1 = fm + (size_t)yi * Ww;
                float v00 = __ldg(r0 + x0), v01 = __ldg(r0 + xi);
                float v10 = __ldg(r1 + x0), v11 = __ldg(r1 + xi);
                float top = fmaf(lx, v01 - v00, v00);
                float bot = fmaf(lx, v11 - v10, v10);
                float t = fmaf(ly, bot - top, top);
                t = valid ? t : 0.0f;
                float s = __ldg(sel + p);
                acc  += fmaxf(s, 0.0f) - s * t;
                prod *= 1.0f + __expf(-fabsf(s));
            }
        }

        // product across 8-lane groups (each factor in (1,2], <=8 pts/thread)
        #pragma unroll
        for (int o = 1; o < 8; o <<= 1) prod *= __shfl_xor_sync(0xFFFFFFFFu, prod, o);
        if ((lane & 7) == 0) acc += __logf(prod);

        #pragma unroll
        for (int o = 16; o; o >>= 1) acc += __shfl_xor_sync(0xFFFFFFFFu, acc, o);
        if (lane == 0) sh[w] = acc;
    }
    __syncthreads();

    if (w == 0) {
        float v = (lane < 8) ? sh[lane] : 0.0f;
        #pragma unroll
        for (int o = 4; o; o >>= 1) v += __shfl_xor_sync(0xFFFFFFFFu, v, o);
        if (lane == 0) {
            atomicAdd(&g_bins[b], v / (float)P);
            atomicAdd(&g_cnt[b], 1);
        }
    }
    __syncthreads();

    // ---- last-block finalize (no separate writer launch) ----
    if (tid == 0) {
        __threadfence();
        unsigned int n = atomicAdd(&g_arrive, 1u);
        s_last = (n == (unsigned int)(gridDim.x - 1));
    }
    __syncthreads();
    if (s_last) {
        if (tid == 0) __threadfence();   // acquire: see all blocks' accumulators
        __syncthreads();
        if (tid == 0) out[0] = g_cls_sum / (float)R;
        if (tid == 1) out[1] = g_box_sum / (float)R;
        if (tid < G) {
            int c = g_cnt[tid];
            out[2 + tid] = (c > 0) ? g_bins[tid] / (float)c : 0.0f;
        }
        __syncthreads();
        // reset for next graph replay
        if (tid == 0) { g_cls_sum = 0.0f; g_box_sum = 0.0f; g_arrive = 0u; }
        if (tid < 128) { g_bins[tid] = 0.0f; g_cnt[tid] = 0; }
    }
}

// ---------------------------------------------------------------------------
// Launch
// ---------------------------------------------------------------------------
extern "C" void kernel_launch(void* const* d_in, const int* in_sizes, int n_in,
                              void* d_out, int out_size) {
    const float* class_logit       = (const float*)d_in[0];
    const float* box_regression    = (const float*)d_in[1];
    const float* regression_target = (const float*)d_in[2];
    const float* mask_logit        = (const float*)d_in[3];
    const float* proposal          = (const float*)d_in[4];
    const float* gt_mask           = (const float*)d_in[5];
    const int*   matched_idx       = (const int*)d_in[6];
    const int*   label             = (const int*)d_in[7];
    float* out = (float*)d_out;

    int R = in_sizes[4] / 4;                         // proposal [R,4]
    int C = in_sizes[0] / R;                         // class_logit [R,C]
    int num_pos = in_sizes[2] / 4;                   // regression_target [P,4]
    long long mm = (long long)in_sizes[3] / ((long long)R * C);
    int Mo = (int)(sqrtf((float)mm) + 0.5f);         // mask_logit [R,C,Mo,Mo]
    int G = out_size - 2;                            // per_gt bins
    long long hw = (long long)in_sizes[5] / G;       // gt_mask [G,H,W]
    int Hh = (int)(sqrtf((float)hw) + 0.5f);
    int Ww = Hh;

    if (Mo == 28) {
        fused_kernel<28><<<R, 256>>>(class_logit, box_regression, regression_target,
                                     mask_logit, proposal, gt_mask,
                                     matched_idx, label, out,
                                     C, Hh, Ww, Mo, num_pos, R, G);
    } else {
        fused_kernel<0><<<R, 256>>>(class_logit, box_regression, regression_target,
                                    mask_logit, proposal, gt_mask,
                                    matched_idx, label, out,
                                    C, Hh, Ww, Mo, num_pos, R, G);
    }
}

// round 5
// speedup vs baseline: 1.0353x; 1.0353x over previous
#include <cuda_runtime.h>
#include <cuda_bf16.h>
#include <math.h>

// Global accumulators (zero at module load; last block resets them each run,
// so every graph replay starts from zeros).
__device__ float        g_bins[128];
__device__ int          g_cnt[128];
__device__ float        g_cls_sum;
__device__ float        g_box_sum;
__device__ unsigned int g_arrive;

// ---------------------------------------------------------------------------
// Single fused kernel: one block (256 thr) per RoI r.
//   warps 0-6 (tid 0..195 active): RoI-align bilinear target + BCE (float4)
//   warp 7: cls CE for row r  (+ box smooth-L1 if r < num_pos)
//   block reduce -> atomicAdd into global accumulators (L2-resident)
//   LAST block (acq_rel arrive, NO per-block L1-flushing fence): writes all
//   outputs via L2 reads and resets accumulators.
// ---------------------------------------------------------------------------
template<int MO>
__global__ void __launch_bounds__(256) fused_kernel(
        const float* __restrict__ class_logit,
        const float* __restrict__ box_regression,
        const float* __restrict__ regression_target,
        const float* __restrict__ mask_logit,
        const float* __restrict__ proposal,
        const float* __restrict__ gt_mask,
        const int* __restrict__ matched_idx,
        const int* __restrict__ label,
        float* __restrict__ out,
        int C, int Hh, int Ww, int Mo_rt, int num_pos, int R, int G) {
    const int Mo = (MO > 0) ? MO : Mo_rt;
    const int P  = Mo * Mo;
    int r    = blockIdx.x;
    int tid  = threadIdx.x;
    int lane = tid & 31;
    int w    = tid >> 5;
    __shared__ float sh[8];
    __shared__ bool  s_last;

    int lab = __ldg(&label[r]);
    int b   = __ldg(&matched_idx[r]);

    float acc = 0.0f;

    if (w == 7) {
        // ---- classification CE for this row ----
        const float* row = class_logit + (size_t)r * C;
        float mx = -INFINITY;
        for (int c = lane; c < C; c += 32) mx = fmaxf(mx, __ldg(row + c));
        #pragma unroll
        for (int o = 16; o; o >>= 1) mx = fmaxf(mx, __shfl_xor_sync(0xFFFFFFFFu, mx, o));
        float s2 = 0.0f;
        for (int c = lane; c < C; c += 32) s2 += __expf(__ldg(row + c) - mx);
        #pragma unroll
        for (int o = 16; o; o >>= 1) s2 += __shfl_xor_sync(0xFFFFFFFFu, s2, o);
        if (lane == 0) atomicAdd(&g_cls_sum, mx + __logf(s2) - __ldg(row + lab));

        // ---- box smooth-L1 for this row (if positive) ----
        if (r < num_pos) {
            float term = 0.0f;
            if (lane < 4) {
                float pred = __ldg(&box_regression[(size_t)r * (C * 4) + lab * 4 + lane]);
                float tgt  = __ldg(&regression_target[r * 4 + lane]);
                float d = fabsf(pred - tgt);
                term = (d < 1.0f) ? 0.5f * d * d : d - 0.5f;
            }
            #pragma unroll
            for (int o = 2; o; o >>= 1) term += __shfl_xor_sync(0xFFFFFFFFu, term, o);
            if (lane == 0) atomicAdd(&g_box_sum, term);
        }
        if (lane == 0) sh[7] = 0.0f;
    } else {
        // ---- mask BCE ----
        float4 box = *(const float4*)(proposal + (size_t)r * 4);
        float x1 = box.x, y1 = box.y, x2 = box.z, y2 = box.w;
        float invMo = 1.0f / (float)Mo;
        float sx = (x2 - x1) * invMo;
        float sy = (y2 - y1) * invMo;
        const float* sel = mask_logit + ((size_t)r * C + lab) * P;
        const float* fm  = gt_mask + (size_t)b * Hh * Ww;

        float prod = 1.0f;

        if (MO == 28) {
            const int q = tid;                 // tid 0..195 active (196 float4 chunks)
            if (q < 196) {
                int iy  = q / 7;
                int ix0 = (q - iy * 7) << 2;
                float y = fmaf((float)iy + 0.5f, sy, y1);
                float4 s4 = __ldg((const float4*)sel + q);

                bool vy = (y > -1.0f) & (y < (float)Hh);
                float yc = fminf(fmaxf(y, 0.0f), (float)(Hh - 1));
                int y0 = (int)yc;
                int yi = min(y0 + 1, Hh - 1);
                float ly = yc - (float)y0;
                const float* r0 = fm + (size_t)y0 * Ww;
                const float* r1 = fm + (size_t)yi * Ww;

                // branch-free: all gathers issue unconditionally (coords clamped)
                #pragma unroll
                for (int j = 0; j < 4; j++) {
                    float s = (j == 0) ? s4.x : (j == 1) ? s4.y : (j == 2) ? s4.z : s4.w;
                    float x = fmaf((float)(ix0 + j) + 0.5f, sx, x1);
                    bool valid = vy & (x > -1.0f) & (x < (float)Ww);
                    float xc = fminf(fmaxf(x, 0.0f), (float)(Ww - 1));
                    int x0 = (int)xc;
                    int xi = min(x0 + 1, Ww - 1);
                    float lx = xc - (float)x0;
                    float v00 = __ldg(r0 + x0);
                    float v01 = __ldg(r0 + xi);
                    float v10 = __ldg(r1 + x0);
                    float v11 = __ldg(r1 + xi);
                    float top = fmaf(lx, v01 - v00, v00);
                    float bot = fmaf(lx, v11 - v10, v10);
                    float t = fmaf(ly, bot - top, top);
                    t = valid ? t : 0.0f;
                    acc  += fmaxf(s, 0.0f) - s * t;
                    prod *= 1.0f + __expf(-fabsf(s));
                }
            }
        } else {
            for (int p = tid; p < P; p += 224) {
                int iy = p / Mo;
                int ix = p - iy * Mo;
                float x = fmaf((float)ix + 0.5f, sx, x1);
                float y = fmaf((float)iy + 0.5f, sy, y1);
                bool valid = (x > -1.0f) & (x < (float)Ww) & (y > -1.0f) & (y < (float)Hh);
                float xc = fminf(fmaxf(x, 0.0f), (float)(Ww - 1));
                float yc = fminf(fmaxf(y, 0.0f), (float)(Hh - 1));
                int x0 = (int)xc, y0 = (int)yc;
                int xi = min(x0 + 1, Ww - 1);
                int yi = min(y0 + 1, Hh - 1);
                float lx = xc - (float)x0, ly = yc - (float)y0;
                const float* r0 = fm + (size_t)y0 * Ww;
                const float* r1 = fm + (size_t)yi * Ww;
                float v00 = __ldg(r0 + x0), v01 = __ldg(r0 + xi);
                float v10 = __ldg(r1 + x0), v11 = __ldg(r1 + xi);
                float top = fmaf(lx, v01 - v00, v00);
                float bot = fmaf(lx, v11 - v10, v10);
                float t = fmaf(ly, bot - top, top);
                t = valid ? t : 0.0f;
                float s = __ldg(sel + p);
                acc  += fmaxf(s, 0.0f) - s * t;
                prod *= 1.0f + __expf(-fabsf(s));
            }
        }

        // product across 8-lane groups (each factor in (1,2], <=8 pts/thread)
        #pragma unroll
        for (int o = 1; o < 8; o <<= 1) prod *= __shfl_xor_sync(0xFFFFFFFFu, prod, o);
        if ((lane & 7) == 0) acc += __logf(prod);

        #pragma unroll
        for (int o = 16; o; o >>= 1) acc += __shfl_xor_sync(0xFFFFFFFFu, acc, o);
        if (lane == 0) sh[w] = acc;
    }
    __syncthreads();

    if (w == 0) {
        float v = (lane < 8) ? sh[lane] : 0.0f;
        #pragma unroll
        for (int o = 4; o; o >>= 1) v += __shfl_xor_sync(0xFFFFFFFFu, v, o);
        if (lane == 0) {
            atomicAdd(&g_bins[b], v / (float)P);
            atomicAdd(&g_cnt[b], 1);
        }
    }
    __syncthreads();

    // ---- last-block finalize: acq_rel arrive atomic, NO L1-flushing fence ----
    if (tid == 0) {
        unsigned int n;
        asm volatile("atom.acq_rel.gpu.add.u32 %0, [%1], 1;"
                     : "=r"(n) : "l"(&g_arrive) : "memory");
        s_last = (n == (unsigned int)(gridDim.x - 1));
    }
    __syncthreads();
    if (s_last) {
        // All other blocks' accumulator atomics are L2-resident and ordered
        // before their release-arrive. Read via L2 (bypass L1).
        if (tid == 0) out[0] = __ldcg(&g_cls_sum) / (float)R;
        if (tid == 1) out[1] = __ldcg(&g_box_sum) / (float)R;
        if (tid < G) {
            int c = __ldcg(&g_cnt[tid]);
            float bsum = __ldcg(&g_bins[tid]);
            out[2 + tid] = (c > 0) ? bsum / (float)c : 0.0f;
        }
        __syncthreads();
        // reset for next graph replay (visible at kernel boundary)
        if (tid == 0) { g_cls_sum = 0.0f; g_box_sum = 0.0f; g_arrive = 0u; }
        if (tid < 128) { g_bins[tid] = 0.0f; g_cnt[tid] = 0; }
    }
}

// ---------------------------------------------------------------------------
// Launch
// ---------------------------------------------------------------------------
extern "C" void kernel_launch(void* const* d_in, const int* in_sizes, int n_in,
                              void* d_out, int out_size) {
    const float* class_logit       = (const float*)d_in[0];
    const float* box_regression    = (const float*)d_in[1];
    const float* regression_target = (const float*)d_in[2];
    const float* mask_logit        = (const float*)d_in[3];
    const float* proposal          = (const float*)d_in[4];
    const float* gt_mask           = (const float*)d_in[5];
    const int*   matched_idx       = (const int*)d_in[6];
    const int*   label             = (const int*)d_in[7];
    float* out = (float*)d_out;

    int R = in_sizes[4] / 4;                         // proposal [R,4]
    int C = in_sizes[0] / R;                         // class_logit [R,C]
    int num_pos = in_sizes[2] / 4;                   // regression_target [P,4]
    long long mm = (long long)in_sizes[3] / ((long long)R * C);
    int Mo = (int)(sqrtf((float)mm) + 0.5f);         // mask_logit [R,C,Mo,Mo]
    int G = out_size - 2;                            // per_gt bins
    long long hw = (long long)in_sizes[5] / G;       // gt_mask [G,H,W]
    int Hh = (int)(sqrtf((float)hw) + 0.5f);
    int Ww = Hh;

    if (Mo == 28) {
        fused_kernel<28><<<R, 256>>>(class_logit, box_regression, regression_target,
                                     mask_logit, proposal, gt_mask,
                                     matched_idx, label, out,
                                     C, Hh, Ww, Mo, num_pos, R, G);
    } else {
        fused_kernel<0><<<R, 256>>>(class_logit, box_regression, regression_target,
                                    mask_logit, proposal, gt_mask,
                                    matched_idx, label, out,
                                    C, Hh, Ww, Mo, num_pos, R, G);
    }
}

// round 6
// speedup vs baseline: 1.1139x; 1.0759x over previous
#include <cuda_runtime.h>
#include <cuda_bf16.h>
#include <math.h>

// Global accumulators (zero at module load; last block resets them each run,
// so every graph replay starts from zeros).
__device__ float        g_bins[128];
__device__ int          g_cnt[128];
__device__ float        g_cls_sum;
__device__ float        g_box_sum;
__device__ unsigned int g_arrive;

// ---------------------------------------------------------------------------
// Single fused kernel: one block (256 thr) per RoI r.
//   warps 0-6 (tid 0..195 active): RoI-align bilinear target + BCE (float4)
//   warp 7: cls CE for row r  (+ box smooth-L1 if r < num_pos)
//   block reduce -> atomicAdd into global accumulators (relaxed, L2-resident)
//   arrive: atom.release.gpu (NO acquire -> NO L1 invalidate on any SM)
//   LAST block: reads accumulators via __ldcg (L2-only, no staleness hazard),
//   writes all outputs, resets globals for the next graph replay.
// ---------------------------------------------------------------------------
template<int MO>
__global__ void __launch_bounds__(256) fused_kernel(
        const float* __restrict__ class_logit,
        const float* __restrict__ box_regression,
        const float* __restrict__ regression_target,
        const float* __restrict__ mask_logit,
        const float* __restrict__ proposal,
        const float* __restrict__ gt_mask,
        const int* __restrict__ matched_idx,
        const int* __restrict__ label,
        float* __restrict__ out,
        int C, int Hh, int Ww, int Mo_rt, int num_pos, int R, int G) {
    const int Mo = (MO > 0) ? MO : Mo_rt;
    const int P  = Mo * Mo;
    int r    = blockIdx.x;
    int tid  = threadIdx.x;
    int lane = tid & 31;
    int w    = tid >> 5;
    __shared__ float sh[8];
    __shared__ bool  s_last;

    int lab = __ldg(&label[r]);
    int b   = __ldg(&matched_idx[r]);

    float acc = 0.0f;

    if (w == 7) {
        // ---- classification CE for this row ----
        const float* row = class_logit + (size_t)r * C;
        float mx = -INFINITY;
        for (int c = lane; c < C; c += 32) mx = fmaxf(mx, __ldg(row + c));
        #pragma unroll
        for (int o = 16; o; o >>= 1) mx = fmaxf(mx, __shfl_xor_sync(0xFFFFFFFFu, mx, o));
        float s2 = 0.0f;
        for (int c = lane; c < C; c += 32) s2 += __expf(__ldg(row + c) - mx);
        #pragma unroll
        for (int o = 16; o; o >>= 1) s2 += __shfl_xor_sync(0xFFFFFFFFu, s2, o);
        if (lane == 0) atomicAdd(&g_cls_sum, mx + __logf(s2) - __ldg(row + lab));

        // ---- box smooth-L1 for this row (if positive) ----
        if (r < num_pos) {
            float term = 0.0f;
            if (lane < 4) {
                float pred = __ldg(&box_regression[(size_t)r * (C * 4) + lab * 4 + lane]);
                float tgt  = __ldg(&regression_target[r * 4 + lane]);
                float d = fabsf(pred - tgt);
                term = (d < 1.0f) ? 0.5f * d * d : d - 0.5f;
            }
            #pragma unroll
            for (int o = 2; o; o >>= 1) term += __shfl_xor_sync(0xFFFFFFFFu, term, o);
            if (lane == 0) atomicAdd(&g_box_sum, term);
        }
        if (lane == 0) sh[7] = 0.0f;
    } else {
        // ---- mask BCE ----
        float4 box = *(const float4*)(proposal + (size_t)r * 4);
        float x1 = box.x, y1 = box.y, x2 = box.z, y2 = box.w;
        float invMo = 1.0f / (float)Mo;
        float sx = (x2 - x1) * invMo;
        float sy = (y2 - y1) * invMo;
        const float* sel = mask_logit + ((size_t)r * C + lab) * P;
        const float* fm  = gt_mask + (size_t)b * Hh * Ww;

        float prod = 1.0f;

        if (MO == 28) {
            const int q = tid;                 // tid 0..195 active (196 float4 chunks)
            if (q < 196) {
                int iy  = q / 7;
                int ix0 = (q - iy * 7) << 2;
                float y = fmaf((float)iy + 0.5f, sy, y1);
                float4 s4 = __ldg((const float4*)sel + q);

                bool vy = (y > -1.0f) & (y < (float)Hh);
                float yc = fminf(fmaxf(y, 0.0f), (float)(Hh - 1));
                int y0 = (int)yc;
                int yi = min(y0 + 1, Hh - 1);
                float ly = yc - (float)y0;
                const float* r0 = fm + (size_t)y0 * Ww;
                const float* r1 = fm + (size_t)yi * Ww;

                // branch-free: all gathers issue unconditionally (coords clamped)
                #pragma unroll
                for (int j = 0; j < 4; j++) {
                    float s = (j == 0) ? s4.x : (j == 1) ? s4.y : (j == 2) ? s4.z : s4.w;
                    float x = fmaf((float)(ix0 + j) + 0.5f, sx, x1);
                    bool valid = vy & (x > -1.0f) & (x < (float)Ww);
                    float xc = fminf(fmaxf(x, 0.0f), (float)(Ww - 1));
                    int x0 = (int)xc;
                    int xi = min(x0 + 1, Ww - 1);
                    float lx = xc - (float)x0;
                    float v00 = __ldg(r0 + x0);
                    float v01 = __ldg(r0 + xi);
                    float v10 = __ldg(r1 + x0);
                    float v11 = __ldg(r1 + xi);
                    float top = fmaf(lx, v01 - v00, v00);
                    float bot = fmaf(lx, v11 - v10, v10);
                    float t = fmaf(ly, bot - top, top);
                    t = valid ? t : 0.0f;
                    acc  += fmaxf(s, 0.0f) - s * t;
                    prod *= 1.0f + __expf(-fabsf(s));
                }
            }
        } else {
            for (int p = tid; p < P; p += 224) {
                int iy = p / Mo;
                int ix = p - iy * Mo;
                float x = fmaf((float)ix + 0.5f, sx, x1);
                float y = fmaf((float)iy + 0.5f, sy, y1);
                bool valid = (x > -1.0f) & (x < (float)Ww) & (y > -1.0f) & (y < (float)Hh);
                float xc = fminf(fmaxf(x, 0.0f), (float)(Ww - 1));
                float yc = fminf(fmaxf(y, 0.0f), (float)(Hh - 1));
                int x0 = (int)xc, y0 = (int)yc;
                int xi = min(x0 + 1, Ww - 1);
                int yi = min(y0 + 1, Hh - 1);
                float lx = xc - (float)x0, ly = yc - (float)y0;
                const float* r0 = fm + (size_t)y0 * Ww;
                const float* r1 = fm + (size_t)yi * Ww;
                float v00 = __ldg(r0 + x0), v01 = __ldg(r0 + xi);
                float v10 = __ldg(r1 + x0), v11 = __ldg(r1 + xi);
                float top = fmaf(lx, v01 - v00, v00);
                float bot = fmaf(lx, v11 - v10, v10);
                float t = fmaf(ly, bot - top, top);
                t = valid ? t : 0.0f;
                float s = __ldg(sel + p);
                acc  += fmaxf(s, 0.0f) - s * t;
                prod *= 1.0f + __expf(-fabsf(s));
            }
        }

        // product across 8-lane groups (each factor in (1,2], <=8 pts/thread)
        #pragma unroll
        for (int o = 1; o < 8; o <<= 1) prod *= __shfl_xor_sync(0xFFFFFFFFu, prod, o);
        if ((lane & 7) == 0) acc += __logf(prod);

        #pragma unroll
        for (int o = 16; o; o >>= 1) acc += __shfl_xor_sync(0xFFFFFFFFu, acc, o);
        if (lane == 0) sh[w] = acc;
    }
    __syncthreads();

    if (w == 0) {
        float v = (lane < 8) ? sh[lane] : 0.0f;
        #pragma unroll
        for (int o = 4; o; o >>= 1) v += __shfl_xor_sync(0xFFFFFFFFu, v, o);
        if (lane == 0) {
            atomicAdd(&g_bins[b], v / (float)P);
            atomicAdd(&g_cnt[b], 1);
        }
    }
    __syncthreads();

    // ---- last-block finalize: RELEASE-only arrive (no L1 invalidate) ----
    if (tid == 0) {
        unsigned int n;
        asm volatile("atom.release.gpu.global.add.u32 %0, [%1], 1;"
                     : "=r"(n) : "l"(&g_arrive) : "memory");
        s_last = (n == (unsigned int)(gridDim.x - 1));
    }
    __syncthreads();
    if (s_last) {
        // Accumulators are L2-resident atomic results; __ldcg reads L2 directly
        // (never L1), so no acquire fence / IVALL is needed.
        if (tid == 0) out[0] = __ldcg(&g_cls_sum) / (float)R;
        if (tid == 1) out[1] = __ldcg(&g_box_sum) / (float)R;
        if (tid < G) {
            int c = __ldcg(&g_cnt[tid]);
            float bsum = __ldcg(&g_bins[tid]);
            out[2 + tid] = (c > 0) ? bsum / (float)c : 0.0f;
        }
        __syncthreads();
        // reset for next graph replay (visible at kernel boundary)
        if (tid == 0) { g_cls_sum = 0.0f; g_box_sum = 0.0f; g_arrive = 0u; }
        if (tid < 128) { g_bins[tid] = 0.0f; g_cnt[tid] = 0; }
    }
}

// ---------------------------------------------------------------------------
// Launch
// ---------------------------------------------------------------------------
extern "C" void kernel_launch(void* const* d_in, const int* in_sizes, int n_in,
                              void* d_out, int out_size) {
    const float* class_logit       = (const float*)d_in[0];
    const float* box_regression    = (const float*)d_in[1];
    const float* regression_target = (const float*)d_in[2];
    const float* mask_logit        = (const float*)d_in[3];
    const float* proposal          = (const float*)d_in[4];
    const float* gt_mask           = (const float*)d_in[5];
    const int*   matched_idx       = (const int*)d_in[6];
    const int*   label             = (const int*)d_in[7];
    float* out = (float*)d_out;

    int R = in_sizes[4] / 4;                         // proposal [R,4]
    int C = in_sizes[0] / R;                         // class_logit [R,C]
    int num_pos = in_sizes[2] / 4;                   // regression_target [P,4]
    long long mm = (long long)in_sizes[3] / ((long long)R * C);
    int Mo = (int)(sqrtf((float)mm) + 0.5f);         // mask_logit [R,C,Mo,Mo]
    int G = out_size - 2;                            // per_gt bins
    long long hw = (long long)in_sizes[5] / G;       // gt_mask [G,H,W]
    int Hh = (int)(sqrtf((float)hw) + 0.5f);
    int Ww = Hh;

    if (Mo == 28) {
        fused_kernel<28><<<R, 256>>>(class_logit, box_regression, regression_target,
                                     mask_logit, proposal, gt_mask,
                                     matched_idx, label, out,
                                     C, Hh, Ww, Mo, num_pos, R, G);
    } else {
        fused_kernel<0><<<R, 256>>>(class_logit, box_regression, regression_target,
                                    mask_logit, proposal, gt_mask,
                                    matched_idx, label, out,
                                    C, Hh, Ww, Mo, num_pos, R, G);
    }
}

// round 7
// speedup vs baseline: 1.2410x; 1.1142x over previous
#include <cuda_runtime.h>
#include <cuda_bf16.h>
#include <math.h>

// Global accumulators (zero at module load; last block resets them each run,
// so every graph replay starts from zeros).
__device__ float        g_bins[128];
__device__ int          g_cnt[128];
__device__ float        g_cls_sum;
__device__ float        g_box_sum;
__device__ unsigned int g_arrive;

// ---------------------------------------------------------------------------
// Single fused kernel: one block (256 thr) per RoI r.
//   warps 0-6: mask BCE. Warp w handles grid rows 4w..4w+3; lane ix (0..27)
//              handles point (row, ix). All 4 gather LDGs of one instruction
//              stay within ONE gt_mask row -> 3-4 L1tex wavefronts per LDG.
//   warp 7:    cls CE for row r (+ box smooth-L1 if r < num_pos)
//   arrive:    atom.release.gpu (no L1 invalidate); last block writes outputs
//              via __ldcg and resets globals.
// ---------------------------------------------------------------------------
template<int MO>
__global__ void __launch_bounds__(256) fused_kernel(
        const float* __restrict__ class_logit,
        const float* __restrict__ box_regression,
        const float* __restrict__ regression_target,
        const float* __restrict__ mask_logit,
        const float* __restrict__ proposal,
        const float* __restrict__ gt_mask,
        const int* __restrict__ matched_idx,
        const int* __restrict__ label,
        float* __restrict__ out,
        int C, int Hh, int Ww, int Mo_rt, int num_pos, int R, int G) {
    const int Mo = (MO > 0) ? MO : Mo_rt;
    const int P  = Mo * Mo;
    int r    = blockIdx.x;
    int tid  = threadIdx.x;
    int lane = tid & 31;
    int w    = tid >> 5;
    __shared__ float sh[8];
    __shared__ bool  s_last;

    int lab = __ldg(&label[r]);
    int b   = __ldg(&matched_idx[r]);

    float acc = 0.0f;

    if (w == 7) {
        // ---- classification CE for this row ----
        const float* row = class_logit + (size_t)r * C;
        float mx = -INFINITY;
        for (int c = lane; c < C; c += 32) mx = fmaxf(mx, __ldg(row + c));
        #pragma unroll
        for (int o = 16; o; o >>= 1) mx = fmaxf(mx, __shfl_xor_sync(0xFFFFFFFFu, mx, o));
        float s2 = 0.0f;
        for (int c = lane; c < C; c += 32) s2 += __expf(__ldg(row + c) - mx);
        #pragma unroll
        for (int o = 16; o; o >>= 1) s2 += __shfl_xor_sync(0xFFFFFFFFu, s2, o);
        if (lane == 0) atomicAdd(&g_cls_sum, mx + __logf(s2) - __ldg(row + lab));

        // ---- box smooth-L1 for this row (if positive) ----
        if (r < num_pos) {
            float term = 0.0f;
            if (lane < 4) {
                float pred = __ldg(&box_regression[(size_t)r * (C * 4) + lab * 4 + lane]);
                float tgt  = __ldg(&regression_target[r * 4 + lane]);
                float d = fabsf(pred - tgt);
                term = (d < 1.0f) ? 0.5f * d * d : d - 0.5f;
            }
            #pragma unroll
            for (int o = 2; o; o >>= 1) term += __shfl_xor_sync(0xFFFFFFFFu, term, o);
            if (lane == 0) atomicAdd(&g_box_sum, term);
        }
        if (lane == 0) sh[7] = 0.0f;
    } else {
        // ---- mask BCE ----
        float4 box = *(const float4*)(proposal + (size_t)r * 4);
        float x1 = box.x, y1 = box.y, x2 = box.z, y2 = box.w;
        float invMo = 1.0f / (float)Mo;
        float sx = (x2 - x1) * invMo;
        float sy = (y2 - y1) * invMo;
        const float* sel = mask_logit + ((size_t)r * C + lab) * P;
        const float* fm  = gt_mask + (size_t)b * Hh * Ww;

        float prod = 1.0f;

        if (MO == 28) {
            const int ix = lane;                 // lanes 0..27 active
            const bool active = ix < 28;

            // x geometry is row-invariant: compute once per thread.
            float x  = fmaf((float)ix + 0.5f, sx, x1);
            bool  vx = (x > -1.0f) & (x < (float)Ww);
            float xc = fminf(fmaxf(x, 0.0f), (float)(Ww - 1));
            int   x0 = (int)xc;
            int   xi = min(x0 + 1, Ww - 1);
            float lx = xc - (float)x0;

            #pragma unroll
            for (int i = 0; i < 4; i++) {
                int row = (w << 2) + i;          // warp w -> rows 4w..4w+3
                float y = fmaf((float)row + 0.5f, sy, y1);
                bool valid = active & vx & (y > -1.0f) & (y < (float)Hh);
                float yc = fminf(fmaxf(y, 0.0f), (float)(Hh - 1));
                int y0 = (int)yc;
                int yi = min(y0 + 1, Hh - 1);
                float ly = yc - (float)y0;
                const float* r0 = fm + (size_t)y0 * Ww;
                const float* r1 = fm + (size_t)yi * Ww;

                // branch-free gathers: all lanes issue (clamped addresses)
                float v00 = __ldg(r0 + x0);
                float v01 = __ldg(r0 + xi);
                float v10 = __ldg(r1 + x0);
                float v11 = __ldg(r1 + xi);
                float s   = active ? __ldg(sel + row * 28 + ix) : 0.0f;

                float top = fmaf(lx, v01 - v00, v00);
                float bot = fmaf(lx, v11 - v10, v10);
                float t = fmaf(ly, bot - top, top);
                t = valid ? t : 0.0f;
                acc += fmaxf(s, 0.0f) - s * t;
                float f = 1.0f + __expf(-fabsf(s));
                prod *= active ? f : 1.0f;
            }
        } else {
            for (int p = tid; p < P; p += 224) {
                int iy = p / Mo;
                int ix = p - iy * Mo;
                float x = fmaf((float)ix + 0.5f, sx, x1);
                float y = fmaf((float)iy + 0.5f, sy, y1);
                bool valid = (x > -1.0f) & (x < (float)Ww) & (y > -1.0f) & (y < (float)Hh);
                float xc = fminf(fmaxf(x, 0.0f), (float)(Ww - 1));
                float yc = fminf(fmaxf(y, 0.0f), (float)(Hh - 1));
                int x0 = (int)xc, y0 = (int)yc;
                int xi = min(x0 + 1, Ww - 1);
                int yi = min(y0 + 1, Hh - 1);
                float lx = xc - (float)x0, ly = yc - (float)y0;
                const float* r0 = fm + (size_t)y0 * Ww;
                const float* r1 = fm + (size_t)yi * Ww;
                float v00 = __ldg(r0 + x0), v01 = __ldg(r0 + xi);
                float v10 = __ldg(r1 + x0), v11 = __ldg(r1 + xi);
                float top = fmaf(lx, v01 - v00, v00);
                float bot = fmaf(lx, v11 - v10, v10);
                float t = fmaf(ly, bot - top, top);
                t = valid ? t : 0.0f;
                float s = __ldg(sel + p);
                acc  += fmaxf(s, 0.0f) - s * t;
                prod *= 1.0f + __expf(-fabsf(s));
            }
        }

        // product across 8-lane groups (factors in (1,2], 4 pts/thread)
        #pragma unroll
        for (int o = 1; o < 8; o <<= 1) prod *= __shfl_xor_sync(0xFFFFFFFFu, prod, o);
        if ((lane & 7) == 0) acc += __logf(prod);

        #pragma unroll
        for (int o = 16; o; o >>= 1) acc += __shfl_xor_sync(0xFFFFFFFFu, acc, o);
        if (lane == 0) sh[w] = acc;
    }
    __syncthreads();

    if (w == 0) {
        float v = (lane < 8) ? sh[lane] : 0.0f;
        #pragma unroll
        for (int o = 4; o; o >>= 1) v += __shfl_xor_sync(0xFFFFFFFFu, v, o);
        if (lane == 0) {
            atomicAdd(&g_bins[b], v / (float)P);
            atomicAdd(&g_cnt[b], 1);
        }
    }
    __syncthreads();

    // ---- last-block finalize: RELEASE-only arrive (no L1 invalidate) ----
    if (tid == 0) {
        unsigned int n;
        asm volatile("atom.release.gpu.global.add.u32 %0, [%1], 1;"
                     : "=r"(n) : "l"(&g_arrive) : "memory");
        s_last = (n == (unsigned int)(gridDim.x - 1));
    }
    __syncthreads();
    if (s_last) {
        // Accumulators are L2-resident atomic results; __ldcg reads L2 directly.
        if (tid == 0) out[0] = __ldcg(&g_cls_sum) / (float)R;
        if (tid == 1) out[1] = __ldcg(&g_box_sum) / (float)R;
        if (tid < G) {
            int c = __ldcg(&g_cnt[tid]);
            float bsum = __ldcg(&g_bins[tid]);
            out[2 + tid] = (c > 0) ? bsum / (float)c : 0.0f;
        }
        __syncthreads();
        // reset for next graph replay (visible at kernel boundary)
        if (tid == 0) { g_cls_sum = 0.0f; g_box_sum = 0.0f; g_arrive = 0u; }
        if (tid < 128) { g_bins[tid] = 0.0f; g_cnt[tid] = 0; }
    }
}

// ---------------------------------------------------------------------------
// Launch
// ---------------------------------------------------------------------------
extern "C" void kernel_launch(void* const* d_in, const int* in_sizes, int n_in,
                              void* d_out, int out_size) {
    const float* class_logit       = (const float*)d_in[0];
    const float* box_regression    = (const float*)d_in[1];
    const float* regression_target = (const float*)d_in[2];
    const float* mask_logit        = (const float*)d_in[3];
    const float* proposal          = (const float*)d_in[4];
    const float* gt_mask           = (const float*)d_in[5];
    const int*   matched_idx       = (const int*)d_in[6];
    const int*   label             = (const int*)d_in[7];
    float* out = (float*)d_out;

    int R = in_sizes[4] / 4;                         // proposal [R,4]
    int C = in_sizes[0] / R;                         // class_logit [R,C]
    int num_pos = in_sizes[2] / 4;                   // regression_target [P,4]
    long long mm = (long long)in_sizes[3] / ((long long)R * C);
    int Mo = (int)(sqrtf((float)mm) + 0.5f);         // mask_logit [R,C,Mo,Mo]
    int G = out_size - 2;                            // per_gt bins
    long long hw = (long long)in_sizes[5] / G;       // gt_mask [G,H,W]
    int Hh = (int)(sqrtf((float)hw) + 0.5f);
    int Ww = Hh;

    if (Mo == 28) {
        fused_kernel<28><<<R, 256>>>(class_logit, box_regression, regression_target,
                                     mask_logit, proposal, gt_mask,
                                     matched_idx, label, out,
                                     C, Hh, Ww, Mo, num_pos, R, G);
    } else {
        fused_kernel<0><<<R, 256>>>(class_logit, box_regression, regression_target,
                                    mask_logit, proposal, gt_mask,
                                    matched_idx, label, out,
                                    C, Hh, Ww, Mo, num_pos, R, G);
    }
}

// round 8
// speedup vs baseline: 1.2678x; 1.0216x over previous
#include <cuda_runtime.h>
#include <cuda_bf16.h>
#include <math.h>

// Global accumulators (zero at module load; last block resets them each run,
// so every graph replay starts from zeros).
__device__ float        g_bins[128];
__device__ int          g_cnt[128];
__device__ float        g_cls_sum;
__device__ float        g_box_sum;
__device__ unsigned int g_arrive;

// ---------------------------------------------------------------------------
// Single fused kernel: one block (256 thr) per RoI r.
//   warps 0-6: mask BCE, one grid row per (warp,iter), lane ix = column.
//              ALL 20 loads (16 gathers + 4 sel) issued before any consume ->
//              MLP ~20 per thread. __launch_bounds__(256,5) gives ptxas the
//              registers to keep them all in flight.
//   warp 7:    cls CE for row r (+ box smooth-L1 if r < num_pos)
//   arrive:    atom.release.gpu (no L1 invalidate); last block writes outputs
//              via __ldcg and resets globals.
// ---------------------------------------------------------------------------
template<int MO>
__global__ void __launch_bounds__(256, 5) fused_kernel(
        const float* __restrict__ class_logit,
        const float* __restrict__ box_regression,
        const float* __restrict__ regression_target,
        const float* __restrict__ mask_logit,
        const float* __restrict__ proposal,
        const float* __restrict__ gt_mask,
        const int* __restrict__ matched_idx,
        const int* __restrict__ label,
        float* __restrict__ out,
        int C, int Hh, int Ww, int Mo_rt, int num_pos, int R, int G) {
    const int Mo = (MO > 0) ? MO : Mo_rt;
    const int P  = Mo * Mo;
    int r    = blockIdx.x;
    int tid  = threadIdx.x;
    int lane = tid & 31;
    int w    = tid >> 5;
    __shared__ float sh[8];
    __shared__ bool  s_last;

    int lab = __ldg(&label[r]);
    int b   = __ldg(&matched_idx[r]);

    float acc = 0.0f;

    if (w == 7) {
        // ---- classification CE for this row ----
        const float* row = class_logit + (size_t)r * C;
        // C=81: lanes cover 81 cols in 3 strided reads; load all, then reduce
        float e0 = (lane      < C) ? __ldg(row + lane)      : -INFINITY;
        float e1 = (lane + 32 < C) ? __ldg(row + lane + 32) : -INFINITY;
        float e2 = (lane + 64 < C) ? __ldg(row + lane + 64) : -INFINITY;
        float mx = fmaxf(e0, fmaxf(e1, e2));
        #pragma unroll
        for (int o = 16; o; o >>= 1) mx = fmaxf(mx, __shfl_xor_sync(0xFFFFFFFFu, mx, o));
        float s2 = 0.0f;
        if (lane      < C) s2 += __expf(e0 - mx);
        if (lane + 32 < C) s2 += __expf(e1 - mx);
        if (lane + 64 < C) s2 += __expf(e2 - mx);
        #pragma unroll
        for (int o = 16; o; o >>= 1) s2 += __shfl_xor_sync(0xFFFFFFFFu, s2, o);
        if (lane == 0) atomicAdd(&g_cls_sum, mx + __logf(s2) - __ldg(row + lab));

        // ---- box smooth-L1 for this row (if positive) ----
        if (r < num_pos) {
            float term = 0.0f;
            if (lane < 4) {
                float pred = __ldg(&box_regression[(size_t)r * (C * 4) + lab * 4 + lane]);
                float tgt  = __ldg(&regression_target[r * 4 + lane]);
                float d = fabsf(pred - tgt);
                term = (d < 1.0f) ? 0.5f * d * d : d - 0.5f;
            }
            #pragma unroll
            for (int o = 2; o; o >>= 1) term += __shfl_xor_sync(0xFFFFFFFFu, term, o);
            if (lane == 0) atomicAdd(&g_box_sum, term);
        }
        if (lane == 0) sh[7] = 0.0f;
    } else {
        // ---- mask BCE ----
        float4 box = *(const float4*)(proposal + (size_t)r * 4);
        float x1 = box.x, y1 = box.y, x2 = box.z, y2 = box.w;
        float invMo = 1.0f / (float)Mo;
        float sx = (x2 - x1) * invMo;
        float sy = (y2 - y1) * invMo;
        const float* sel = mask_logit + ((size_t)r * C + lab) * P;
        const float* fm  = gt_mask + (size_t)b * Hh * Ww;

        float prod = 1.0f;

        if (MO == 28) {
            const int ix = lane;                 // lanes 0..27 active
            const bool active = ix < 28;

            // x geometry is row-invariant
            float x  = fmaf((float)ix + 0.5f, sx, x1);
            bool  vx = (x > -1.0f) & (x < (float)Ww);
            float xc = fminf(fmaxf(x, 0.0f), (float)(Ww - 1));
            int   x0 = (int)xc;
            int   xi = min(x0 + 1, Ww - 1);
            float lx = xc - (float)x0;

            // ---- phase 1: geometry for all 4 rows ----
            float ly[4]; bool vrow[4];
            const float* rp0[4]; const float* rp1[4];
            #pragma unroll
            for (int i = 0; i < 4; i++) {
                int row = (w << 2) + i;
                float y = fmaf((float)row + 0.5f, sy, y1);
                vrow[i] = active & vx & (y > -1.0f) & (y < (float)Hh);
                float yc = fminf(fmaxf(y, 0.0f), (float)(Hh - 1));
                int y0 = (int)yc;
                int yi = min(y0 + 1, Hh - 1);
                ly[i] = yc - (float)y0;
                rp0[i] = fm + (size_t)y0 * Ww;
                rp1[i] = fm + (size_t)yi * Ww;
            }
            // ---- phase 2: issue ALL loads before any consume ----
            float v00[4], v01[4], v10[4], v11[4], sl[4];
            #pragma unroll
            for (int i = 0; i < 4; i++) {
                v00[i] = __ldg(rp0[i] + x0);
                v01[i] = __ldg(rp0[i] + xi);
                v10[i] = __ldg(rp1[i] + x0);
                v11[i] = __ldg(rp1[i] + xi);
            }
            #pragma unroll
            for (int i = 0; i < 4; i++) {
                int row = (w << 2) + i;
                sl[i] = active ? __ldg(sel + row * 28 + ix) : 0.0f;
            }
            // ---- phase 3: consume ----
            #pragma unroll
            for (int i = 0; i < 4; i++) {
                float top = fmaf(lx, v01[i] - v00[i], v00[i]);
                float bot = fmaf(lx, v11[i] - v10[i], v10[i]);
                float t = fmaf(ly[i], bot - top, top);
                t = vrow[i] ? t : 0.0f;
                float s = sl[i];
                acc += fmaxf(s, 0.0f) - s * t;
                float f = 1.0f + __expf(-fabsf(s));
                prod *= active ? f : 1.0f;
            }
        } else {
            for (int p = tid; p < P; p += 224) {
                int iy = p / Mo;
                int ix = p - iy * Mo;
                float x = fmaf((float)ix + 0.5f, sx, x1);
                float y = fmaf((float)iy + 0.5f, sy, y1);
                bool valid = (x > -1.0f) & (x < (float)Ww) & (y > -1.0f) & (y < (float)Hh);
                float xc = fminf(fmaxf(x, 0.0f), (float)(Ww - 1));
                float yc = fminf(fmaxf(y, 0.0f), (float)(Hh - 1));
                int x0 = (int)xc, y0 = (int)yc;
                int xi = min(x0 + 1, Ww - 1);
                int yi = min(y0 + 1, Hh - 1);
                float lx = xc - (float)x0, ly = yc - (float)y0;
                const float* r0 = fm + (size_t)y0 * Ww;
                const float* r1 = fm + (size_t)yi * Ww;
                float v00 = __ldg(r0 + x0), v01 = __ldg(r0 + xi);
                float v10 = __ldg(r1 + x0), v11 = __ldg(r1 + xi);
                float top = fmaf(lx, v01 - v00, v00);
                float bot = fmaf(lx, v11 - v10, v10);
                float t = fmaf(ly, bot - top, top);
                t = valid ? t : 0.0f;
                float s = __ldg(sel + p);
                acc  += fmaxf(s, 0.0f) - s * t;
                prod *= 1.0f + __expf(-fabsf(s));
            }
        }

        // product across 8-lane groups (factors in (1,2], 4 pts/thread)
        #pragma unroll
        for (int o = 1; o < 8; o <<= 1) prod *= __shfl_xor_sync(0xFFFFFFFFu, prod, o);
        if ((lane & 7) == 0) acc += __logf(prod);

        #pragma unroll
        for (int o = 16; o; o >>= 1) acc += __shfl_xor_sync(0xFFFFFFFFu, acc, o);
        if (lane == 0) sh[w] = acc;
    }
    __syncthreads();

    if (w == 0) {
        float v = (lane < 8) ? sh[lane] : 0.0f;
        #pragma unroll
        for (int o = 4; o; o >>= 1) v += __shfl_xor_sync(0xFFFFFFFFu, v, o);
        if (lane == 0) {
            atomicAdd(&g_bins[b], v / (float)P);
            atomicAdd(&g_cnt[b], 1);
        }
    }
    __syncthreads();

    // ---- last-block finalize: RELEASE-only arrive (no L1 invalidate) ----
    if (tid == 0) {
        unsigned int n;
        asm volatile("atom.release.gpu.global.add.u32 %0, [%1], 1;"
                     : "=r"(n) : "l"(&g_arrive) : "memory");
        s_last = (n == (unsigned int)(gridDim.x - 1));
    }
    __syncthreads();
    if (s_last) {
        // Accumulators are L2-resident atomic results; __ldcg reads L2 directly.
        if (tid == 0) out[0] = __ldcg(&g_cls_sum) / (float)R;
        if (tid == 1) out[1] = __ldcg(&g_box_sum) / (float)R;
        if (tid < G) {
            int c = __ldcg(&g_cnt[tid]);
            float bsum = __ldcg(&g_bins[tid]);
            out[2 + tid] = (c > 0) ? bsum / (float)c : 0.0f;
        }
        __syncthreads();
        // reset for next graph replay (visible at kernel boundary)
        if (tid == 0) { g_cls_sum = 0.0f; g_box_sum = 0.0f; g_arrive = 0u; }
        if (tid < 128) { g_bins[tid] = 0.0f; g_cnt[tid] = 0; }
    }
}

// ---------------------------------------------------------------------------
// Launch
// ---------------------------------------------------------------------------
extern "C" void kernel_launch(void* const* d_in, const int* in_sizes, int n_in,
                              void* d_out, int out_size) {
    const float* class_logit       = (const float*)d_in[0];
    const float* box_regression    = (const float*)d_in[1];
    const float* regression_target = (const float*)d_in[2];
    const float* mask_logit        = (const float*)d_in[3];
    const float* proposal          = (const float*)d_in[4];
    const float* gt_mask           = (const float*)d_in[5];
    const int*   matched_idx       = (const int*)d_in[6];
    const int*   label             = (const int*)d_in[7];
    float* out = (float*)d_out;

    int R = in_sizes[4] / 4;                         // proposal [R,4]
    int C = in_sizes[0] / R;                         // class_logit [R,C]
    int num_pos = in_sizes[2] / 4;                   // regression_target [P,4]
    long long mm = (long long)in_sizes[3] / ((long long)R * C);
    int Mo = (int)(sqrtf((float)mm) + 0.5f);         // mask_logit [R,C,Mo,Mo]
    int G = out_size - 2;                            // per_gt bins
    long long hw = (long long)in_sizes[5] / G;       // gt_mask [G,H,W]
    int Hh = (int)(sqrtf((float)hw) + 0.5f);
    int Ww = Hh;

    if (Mo == 28) {
        fused_kernel<28><<<R, 256>>>(class_logit, box_regression, regression_target,
                                     mask_logit, proposal, gt_mask,
                                     matched_idx, label, out,
                                     C, Hh, Ww, Mo, num_pos, R, G);
    } else {
        fused_kernel<0><<<R, 256>>>(class_logit, box_regression, regression_target,
                                    mask_logit, proposal, gt_mask,
                                    matched_idx, label, out,
                                    C, Hh, Ww, Mo, num_pos, R, G);
    }
}